// round 9
// baseline (speedup 1.0000x reference)
#include <cuda_runtime.h>
#include <cuda_bf16.h>
#include <math.h>
#include <stdint.h>

// Problem constants
#define Bn 512
#define En 512
#define Cn 100000
#define NTILES 782            // ceil(100000/128)
#define S_SCALE 30.0f
#define SM_MARGIN 10.5f       // S*M = 30*0.35
#define LAMDA 0.01f
#define ALPHA_C 0.5f
#define EPS_C 1e-6f

#define BSTRIDE 520           // Bs row stride in bf16 (512 + 8 pad)
#define SMEM_GEMM (128 * BSTRIDE * 2 + 2 * 128 * 40 * 2)   // 133120 + 20480 = 153600

// ------------------------- device scratch (static, no allocation) ----------
__device__ int   g_lab[Bn];
__device__ float g_inv_e[Bn];
__device__ __nv_bfloat16 g_emb_bf[Bn * En];
__device__ float g_tgt[Bn];
__device__ float g_pmax[(size_t)Bn * NTILES];
__device__ float g_psum[(size_t)Bn * NTILES];
__device__ float g_pamv[(size_t)Bn * NTILES];
__device__ int   g_pami[(size_t)Bn * NTILES];
__device__ float g_rowloss[Bn];
__device__ int   g_correct[Bn];
__device__ float g_closs;
__device__ float g_appear[Bn];

__device__ __forceinline__ float neg_inf() { return __int_as_float(0xff800000); }

__device__ __forceinline__ void comb_ms(float& m, float& s, float m2, float s2) {
    if (m2 == neg_inf()) return;
    if (m2 > m) { s = s * __expf(m - m2) + s2; m = m2; }
    else        { s += s2 * __expf(m2 - m); }
}

// ------------------------- K-1: decode labels (int32 vs int64 autodetect) --
__global__ void decode_labels_k(const void* __restrict__ labraw) {
    const long long* l64 = (const long long*)labraw;
    const int*       l32 = (const int*)labraw;
    int t = threadIdx.x;               // 256 threads
    long long v = l64[t];              // within first 2048 bytes: always safe
    int valid = (v >= 0 && v < (long long)Cn) ? 1 : 0;
    #pragma unroll
    for (int o = 16; o; o >>= 1) valid &= __shfl_xor_sync(0xffffffffu, valid, o);
    __shared__ int sv[8];
    if ((t & 31) == 0) sv[t >> 5] = valid;
    __syncthreads();
    int all64 = sv[0] & sv[1] & sv[2] & sv[3] & sv[4] & sv[5] & sv[6] & sv[7];
    if (all64) {
        g_lab[t]       = (int)l64[t];
        g_lab[t + 256] = (int)l64[t + 256];
    } else {
        g_lab[t]       = l32[t];
        g_lab[t + 256] = l32[t + 256];
    }
}

// ------------------------- K0: embedding norms + bf16 ----------------------
__global__ void prep_emb_k(const float* __restrict__ emb) {
    int b = blockIdx.x;            // 512 blocks
    int t = threadIdx.x;           // 128 threads
    float4 v = reinterpret_cast<const float4*>(emb + (size_t)b * En)[t];
    float ss = v.x * v.x + v.y * v.y + v.z * v.z + v.w * v.w;
    #pragma unroll
    for (int o = 16; o; o >>= 1) ss += __shfl_xor_sync(0xffffffffu, ss, o);
    __shared__ float sp[4];
    if ((t & 31) == 0) sp[t >> 5] = ss;
    __syncthreads();
    if (t == 0) {
        g_inv_e[b] = rsqrtf(sp[0] + sp[1] + sp[2] + sp[3]);
        if (b == 0) g_closs = 0.0f;
    }
    __nv_bfloat162* dst = reinterpret_cast<__nv_bfloat162*>(g_emb_bf + (size_t)b * En);
    dst[t * 2]     = __floats2bfloat162_rn(v.x, v.y);
    dst[t * 2 + 1] = __floats2bfloat162_rn(v.z, v.w);
}

// ------------------------- K0b: appear counts ------------------------------
__global__ void appear_k() {
    __shared__ int labs[Bn];
    int t = threadIdx.x;
    labs[t] = g_lab[t];
    __syncthreads();
    int mine = labs[t], cnt = 0;
    #pragma unroll 8
    for (int i = 0; i < Bn; i++) cnt += (labs[i] == mine);
    g_appear[t] = (float)cnt;
}

// ------------------------- K1: exact fp32 target logit (own norm) ----------
__global__ __launch_bounds__(256) void tgt_k(const float* __restrict__ emb,
                                             const float* __restrict__ w) {
    int warp = threadIdx.x >> 5, lane = threadIdx.x & 31;
    int b = blockIdx.x * 8 + warp;          // 64*8 = 512
    int lab = g_lab[b];
    const float4* e4 = reinterpret_cast<const float4*>(emb + (size_t)b * En);
    const float4* w4 = reinterpret_cast<const float4*>(w + (size_t)lab * En);
    float dot = 0.f, ssw = 0.f;
    #pragma unroll
    for (int p = 0; p < 4; p++) {
        float4 a = e4[lane + p * 32];
        float4 c = w4[lane + p * 32];
        dot += a.x * c.x + a.y * c.y + a.z * c.z + a.w * c.w;
        ssw += c.x * c.x + c.y * c.y + c.z * c.z + c.w * c.w;
    }
    #pragma unroll
    for (int o = 16; o; o >>= 1) {
        dot += __shfl_xor_sync(0xffffffffu, dot, o);
        ssw += __shfl_xor_sync(0xffffffffu, ssw, o);
    }
    if (lane == 0)
        g_tgt[b] = S_SCALE * dot * g_inv_e[b] * rsqrtf(ssw) - SM_MARGIN;
}

// ------------------------- K2: fused norm+convert+GEMM+softmax -------------
__device__ __forceinline__ void mma16816(float* d, const uint32_t* a, const uint32_t* b) {
    asm volatile(
        "mma.sync.aligned.m16n8k16.row.col.f32.bf16.bf16.f32 "
        "{%0,%1,%2,%3}, {%4,%5,%6,%7}, {%8,%9}, {%0,%1,%2,%3};\n"
        : "+f"(d[0]), "+f"(d[1]), "+f"(d[2]), "+f"(d[3])
        : "r"(a[0]), "r"(a[1]), "r"(a[2]), "r"(a[3]), "r"(b[0]), "r"(b[1]));
}

// grid = (NTILES). Block 512 threads: converts its 128x512 fp32 W tile to a
// resident bf16 smem tile (computing inv_w in-block), then loops all 4 m-tiles.
__global__ __launch_bounds__(512, 1) void gemm_fused_k(const float* __restrict__ w) {
    extern __shared__ __align__(16) char dyn[];
    __nv_bfloat16* Bs = reinterpret_cast<__nv_bfloat16*>(dyn);             // [128][BSTRIDE]
    __nv_bfloat16* As = reinterpret_cast<__nv_bfloat16*>(dyn + 128 * BSTRIDE * 2); // [2][128][40]

    __shared__ float s_invw[128];
    __shared__ int   s_lab[128];
    __shared__ float s_inve[128];
    __shared__ float sm_m[4][128], sm_s[4][128], sm_av[4][128];
    __shared__ int   sm_ai[4][128];

    const int tid  = threadIdx.x;
    const int warp = tid >> 5, lane = tid & 31;
    const int wm = warp & 3, wn = warp >> 2;       // 4 (M) x 4 (N) warps
    const int gid = lane >> 2, t4 = lane & 3;
    const int n0 = blockIdx.x * 128;

    // ---- fill phase: fp32 W -> bf16 smem + row inverse norms ----
    {
        int r = tid >> 2, q = tid & 3;             // 4 threads per row
        int gn = n0 + r;
        size_t gr = (gn < Cn) ? (size_t)gn : (size_t)(Cn - 1);
        const float4* src = reinterpret_cast<const float4*>(w + gr * En);
        float ss = 0.f;
        #pragma unroll 8
        for (int j = 0; j < 32; j++) {
            int f = j * 4 + q;                     // float4 index within row
            float4 v = src[f];
            ss += v.x * v.x + v.y * v.y + v.z * v.z + v.w * v.w;
            __nv_bfloat162* d = reinterpret_cast<__nv_bfloat162*>(&Bs[r * BSTRIDE + f * 4]);
            d[0] = __floats2bfloat162_rn(v.x, v.y);
            d[1] = __floats2bfloat162_rn(v.z, v.w);
        }
        ss += __shfl_xor_sync(0xffffffffu, ss, 1);
        ss += __shfl_xor_sync(0xffffffffu, ss, 2);
        if (q == 0) s_invw[r] = rsqrtf(ss);
    }
    __syncthreads();

    auto load_a = [&](int st, int m0, int kb) {
        int row = tid >> 2, seg = tid & 3;         // 512 threads = 128 rows x 4 segs
        uint32_t dst = (uint32_t)__cvta_generic_to_shared(&As[(st * 128 + row) * 40 + seg * 8]);
        const void* src = &g_emb_bf[(size_t)(m0 + row) * En + kb + seg * 8];
        asm volatile("cp.async.cg.shared.global [%0], [%1], 16;\n" :: "r"(dst), "l"(src));
        asm volatile("cp.async.commit_group;\n");
    };

    #pragma unroll 1
    for (int mt0 = 0; mt0 < 4; mt0++) {
        const int m0 = mt0 * 128;
        if (tid < 128) {
            s_lab[tid]  = g_lab[m0 + tid];
            s_inve[tid] = g_inv_e[m0 + tid];
        }

        float acc[2][4][4];
        #pragma unroll
        for (int a = 0; a < 2; a++)
            #pragma unroll
            for (int b = 0; b < 4; b++)
                #pragma unroll
                for (int c = 0; c < 4; c++) acc[a][b][c] = 0.f;

        load_a(0, m0, 0);
        load_a(1, m0, 32);
        #pragma unroll 1
        for (int ks = 0; ks < 16; ks++) {
            int st = ks & 1;
            if (ks < 15) asm volatile("cp.async.wait_group 1;\n");
            else         asm volatile("cp.async.wait_group 0;\n");
            __syncthreads();
            #pragma unroll
            for (int kk = 0; kk < 32; kk += 16) {
                int kg = ks * 32 + kk;
                uint32_t afr[2][4], bfr[4][2];
                #pragma unroll
                for (int m2 = 0; m2 < 2; m2++) {
                    int r = wm * 32 + m2 * 16 + gid;
                    afr[m2][0] = *(const uint32_t*)&As[(st * 128 + r) * 40 + kk + t4 * 2];
                    afr[m2][1] = *(const uint32_t*)&As[(st * 128 + r + 8) * 40 + kk + t4 * 2];
                    afr[m2][2] = *(const uint32_t*)&As[(st * 128 + r) * 40 + kk + t4 * 2 + 8];
                    afr[m2][3] = *(const uint32_t*)&As[(st * 128 + r + 8) * 40 + kk + t4 * 2 + 8];
                }
                #pragma unroll
                for (int nt = 0; nt < 4; nt++) {
                    int c = wn * 32 + nt * 8 + gid;
                    bfr[nt][0] = *(const uint32_t*)&Bs[c * BSTRIDE + kg + t4 * 2];
                    bfr[nt][1] = *(const uint32_t*)&Bs[c * BSTRIDE + kg + t4 * 2 + 8];
                }
                #pragma unroll
                for (int m2 = 0; m2 < 2; m2++)
                    #pragma unroll
                    for (int nt = 0; nt < 4; nt++)
                        mma16816(acc[m2][nt], afr[m2], bfr[nt]);
            }
            __syncthreads();                       // retire reads of stage st
            if (ks + 2 < 16) load_a(st, m0, (ks + 2) * 32);
        }

        // ---- epilogue: register-level online softmax/argmax partials ----
        #pragma unroll
        for (int m2 = 0; m2 < 2; m2++) {
            #pragma unroll
            for (int h = 0; h < 2; h++) {
                int rloc = wm * 32 + m2 * 16 + gid + h * 8;
                int lab  = s_lab[rloc];
                float sc = S_SCALE * s_inve[rloc];
                float mr = neg_inf(), sr = 0.f, av = neg_inf();
                int ai = 0x7fffffff;
                #pragma unroll
                for (int nt = 0; nt < 4; nt++) {
                    #pragma unroll
                    for (int j = 0; j < 2; j++) {
                        int col = wn * 32 + nt * 8 + t4 * 2 + j;
                        int cg = n0 + col;
                        if (cg < Cn) {
                            float l = acc[m2][nt][h * 2 + j] * sc * s_invw[col];
                            if (cg == lab) l -= SM_MARGIN;
                            if (l > av || (l == av && cg < ai)) { av = l; ai = cg; }
                            if (l > mr) { sr = sr * __expf(mr - l) + 1.f; mr = l; }
                            else        { sr += __expf(l - mr); }
                        }
                    }
                }
                #pragma unroll
                for (int o = 1; o <= 2; o <<= 1) {
                    float m2v = __shfl_xor_sync(0xffffffffu, mr, o);
                    float s2v = __shfl_xor_sync(0xffffffffu, sr, o);
                    comb_ms(mr, sr, m2v, s2v);
                    float v2 = __shfl_xor_sync(0xffffffffu, av, o);
                    int   i2 = __shfl_xor_sync(0xffffffffu, ai, o);
                    if (v2 > av || (v2 == av && i2 < ai)) { av = v2; ai = i2; }
                }
                if (t4 == 0) {
                    sm_m[wn][rloc]  = mr;
                    sm_s[wn][rloc]  = sr;
                    sm_av[wn][rloc] = av;
                    sm_ai[wn][rloc] = ai;
                }
            }
        }
        __syncthreads();
        if (tid < 128) {
            float m = neg_inf(), s = 0.f, av = neg_inf();
            int ai = 0x7fffffff;
            #pragma unroll
            for (int wq = 0; wq < 4; wq++) {
                comb_ms(m, s, sm_m[wq][tid], sm_s[wq][tid]);
                float v = sm_av[wq][tid]; int i = sm_ai[wq][tid];
                if (v > av || (v == av && i < ai)) { av = v; ai = i; }
            }
            size_t o = (size_t)(m0 + tid) * NTILES + blockIdx.x;
            g_pmax[o] = m; g_psum[o] = s; g_pamv[o] = av; g_pami[o] = ai;
        }
        __syncthreads();                           // combine arrays reused next m-tile
    }
}

// ------------------------- K3: per-row LSE + argmax reduce -----------------
__global__ void reduce_rows_k() {
    int gw = (blockIdx.x * blockDim.x + threadIdx.x) >> 5;  // warp per row
    int lane = threadIdx.x & 31;
    if (gw >= Bn) return;
    float m = neg_inf(), s = 0.f, av = neg_inf();
    int ai = 0x7fffffff;
    const float* pm = g_pmax + (size_t)gw * NTILES;
    const float* ps = g_psum + (size_t)gw * NTILES;
    const float* pv = g_pamv + (size_t)gw * NTILES;
    const int*   pi = g_pami + (size_t)gw * NTILES;
    for (int t = lane; t < NTILES; t += 32) {
        comb_ms(m, s, pm[t], ps[t]);
        float v = pv[t]; int i = pi[t];
        if (v > av || (v == av && i < ai)) { av = v; ai = i; }
    }
    #pragma unroll
    for (int o = 16; o; o >>= 1) {
        float m2 = __shfl_xor_sync(0xffffffffu, m, o);
        float s2 = __shfl_xor_sync(0xffffffffu, s, o);
        comb_ms(m, s, m2, s2);
        float v2 = __shfl_xor_sync(0xffffffffu, av, o);
        int   i2 = __shfl_xor_sync(0xffffffffu, ai, o);
        if (v2 > av || (v2 == av && i2 < ai)) { av = v2; ai = i2; }
    }
    if (lane == 0) {
        float lse = m + logf(s);
        g_rowloss[gw] = lse - g_tgt[gw];
        g_correct[gw] = (ai == g_lab[gw]) ? 1 : 0;
    }
}

// ------------------------- K4: copy centers -> out -------------------------
__global__ void copy_centers_k(const float* __restrict__ centers, float* __restrict__ out) {
    size_t i = (size_t)blockIdx.x * blockDim.x + threadIdx.x;   // float2 index
    const float2* src = reinterpret_cast<const float2*>(centers);
    float2* dst = reinterpret_cast<float2*>(out);
    dst[i] = src[i];
}

// ------------------------- K5: scatter update + center loss (fused) --------
__global__ void scatter_closs_k(const float* __restrict__ emb,
                                const float* __restrict__ centers,
                                float* __restrict__ outc) {
    int b = blockIdx.x;
    int r = g_lab[b];
    float coef = ALPHA_C / (g_appear[b] + EPS_C);
    const float* e = emb + (size_t)b * En;
    const float* c = centers + (size_t)r * En;
    float* o = outc + (size_t)r * En;
    float ss = 0.f;
    for (int i = threadIdx.x; i < En; i += 128) {
        float d = e[i] - c[i];
        atomicAdd(&o[i], coef * d);
        ss += d * d;
    }
    #pragma unroll
    for (int of = 16; of; of >>= 1) ss += __shfl_xor_sync(0xffffffffu, ss, of);
    __shared__ float sp[4];
    int warp = threadIdx.x >> 5, lane = threadIdx.x & 31;
    if (lane == 0) sp[warp] = ss;
    __syncthreads();
    if (threadIdx.x == 0)
        atomicAdd(&g_closs, sp[0] + sp[1] + sp[2] + sp[3]);
}

// ------------------------- K6: finalize scalars ----------------------------
__global__ void finalize_k(float* __restrict__ out) {
    int tid = threadIdx.x;  // 512
    float sl = g_rowloss[tid];
    int   sc = g_correct[tid];
    #pragma unroll
    for (int o = 16; o; o >>= 1) {
        sl += __shfl_xor_sync(0xffffffffu, sl, o);
        sc += __shfl_xor_sync(0xffffffffu, sc, o);
    }
    __shared__ float sm_l[16];
    __shared__ int   sm_c[16];
    if ((tid & 31) == 0) { sm_l[tid >> 5] = sl; sm_c[tid >> 5] = sc; }
    __syncthreads();
    if (tid == 0) {
        float L = 0.f; int Cc = 0;
        #pragma unroll
        for (int i = 0; i < 16; i++) { L += sm_l[i]; Cc += sm_c[i]; }
        out[0] = 100.0f * (float)Cc / (float)Bn;
        out[1] = L / (float)Bn + LAMDA * (g_closs / (float)(Bn * En));
    }
}

// ------------------------- launcher ---------------------------------------
extern "C" void kernel_launch(void* const* d_in, const int* in_sizes, int n_in,
                              void* d_out, int out_size) {
    (void)in_sizes; (void)n_in; (void)out_size;
    const float* emb = (const float*)d_in[0];
    const float* w   = (const float*)d_in[1];
    const float* cen = (const float*)d_in[2];
    const void*  lab = d_in[3];
    float* out = (float*)d_out;

    cudaFuncSetAttribute(gemm_fused_k,
                         cudaFuncAttributeMaxDynamicSharedMemorySize, SMEM_GEMM);

    decode_labels_k<<<1, 256>>>(lab);
    prep_emb_k<<<Bn, 128>>>(emb);
    appear_k<<<1, Bn>>>();
    tgt_k<<<Bn / 8, 256>>>(emb, w);
    copy_centers_k<<<100000, 256>>>(cen, out + 2);
    gemm_fused_k<<<NTILES, 512, SMEM_GEMM>>>(w);
    reduce_rows_k<<<64, 256>>>();
    scatter_closs_k<<<Bn, 128>>>(emb, cen, out + 2);
    finalize_k<<<1, Bn>>>(out);
}

// round 12
// speedup vs baseline: 1.2540x; 1.2540x over previous
#include <cuda_runtime.h>
#include <cuda_bf16.h>
#include <math.h>
#include <stdint.h>

// Problem constants
#define Bn 512
#define En 512
#define Cn 100000
#define NTILES 782            // ceil(100000/128)
#define S_SCALE 30.0f
#define SM_MARGIN 10.5f       // S*M
#define LAMDA 0.01f
#define ALPHA_C 0.5f
#define EPS_C 1e-6f
#define LOG2E 1.4426950408889634f
#define M2_MARGIN (10.5f * 1.4426950408889634f)   // margin in log2 units

#define SMEM_DYN (2 * 128 * 40 * 2 * 2)           // As+Bs double-buffered = 40960 B
#define CPY2_TOTAL 25600000                        // centers in float2 (51.2M floats)
#define CPY2_PER_BLK 8192                          // ceil over 3128 blocks

// ------------------------- device scratch (static, no allocation) ----------
__device__ int   g_lab[Bn];
__device__ float g_inv_e[Bn];
__device__ __nv_bfloat16 g_emb_bf[Bn * En];
__device__ float g_inv_w[Cn];
__device__ __nv_bfloat16 g_w_bf[(size_t)Cn * En];
__device__ float g_tgt[Bn];
__device__ float g_psum[(size_t)Bn * NTILES];     // raw sumexp partials
__device__ float g_pmax[(size_t)Bn * NTILES];     // margined max partials (log2 units)
__device__ float g_rowloss[Bn];
__device__ int   g_correct[Bn];
__device__ float g_closs;
__device__ float g_appear[Bn];

__device__ __forceinline__ float ex2(float x) {
    float r;
    asm("ex2.approx.f32 %0, %1;" : "=f"(r) : "f"(x));
    return r;
}

// ------------------------- K-1: decode labels (int32 vs int64 autodetect) --
__global__ void decode_labels_k(const void* __restrict__ labraw) {
    const long long* l64 = (const long long*)labraw;
    const int*       l32 = (const int*)labraw;
    int t = threadIdx.x;               // 256 threads
    long long v = l64[t];              // first 2048 bytes: safe in both layouts
    int valid = (v >= 0 && v < (long long)Cn) ? 1 : 0;
    #pragma unroll
    for (int o = 16; o; o >>= 1) valid &= __shfl_xor_sync(0xffffffffu, valid, o);
    __shared__ int sv[8];
    if ((t & 31) == 0) sv[t >> 5] = valid;
    __syncthreads();
    int all64 = sv[0] & sv[1] & sv[2] & sv[3] & sv[4] & sv[5] & sv[6] & sv[7];
    if (all64) {
        g_lab[t]       = (int)l64[t];
        g_lab[t + 256] = (int)l64[t + 256];
    } else {
        g_lab[t]       = l32[t];
        g_lab[t + 256] = l32[t + 256];
    }
}

// ------------------------- K0: embedding norms + bf16 ----------------------
__global__ void prep_emb_k(const float* __restrict__ emb) {
    int b = blockIdx.x;            // 512 blocks
    int t = threadIdx.x;           // 128 threads
    float4 v = reinterpret_cast<const float4*>(emb + (size_t)b * En)[t];
    float ss = v.x * v.x + v.y * v.y + v.z * v.z + v.w * v.w;
    #pragma unroll
    for (int o = 16; o; o >>= 1) ss += __shfl_xor_sync(0xffffffffu, ss, o);
    __shared__ float sp[4];
    if ((t & 31) == 0) sp[t >> 5] = ss;
    __syncthreads();
    if (t == 0) {
        g_inv_e[b] = rsqrtf(sp[0] + sp[1] + sp[2] + sp[3]);
        if (b == 0) g_closs = 0.0f;
    }
    __nv_bfloat162* dst = reinterpret_cast<__nv_bfloat162*>(g_emb_bf + (size_t)b * En);
    dst[t * 2]     = __floats2bfloat162_rn(v.x, v.y);
    dst[t * 2 + 1] = __floats2bfloat162_rn(v.z, v.w);
}

// ------------------------- K0b: appear counts ------------------------------
__global__ void appear_k() {
    __shared__ int labs[Bn];
    int t = threadIdx.x;
    labs[t] = g_lab[t];
    __syncthreads();
    int mine = labs[t], cnt = 0;
    #pragma unroll 8
    for (int i = 0; i < Bn; i++) cnt += (labs[i] == mine);
    g_appear[t] = (float)cnt;
}

// ------------------------- K1: weight norms + bf16 (warp per row) ----------
__global__ __launch_bounds__(256) void prep_w_k(const float* __restrict__ w) {
    int warp = threadIdx.x >> 5, lane = threadIdx.x & 31;
    int r = blockIdx.x * 8 + warp;          // 12500*8 = 100000 exactly
    const float4* src = reinterpret_cast<const float4*>(w + (size_t)r * En);
    float4 v[4];
    float ss = 0.f;
    #pragma unroll
    for (int p = 0; p < 4; p++) {
        v[p] = src[lane + p * 32];
        ss += v[p].x * v[p].x + v[p].y * v[p].y + v[p].z * v[p].z + v[p].w * v[p].w;
    }
    #pragma unroll
    for (int o = 16; o; o >>= 1) ss += __shfl_xor_sync(0xffffffffu, ss, o);
    if (lane == 0) g_inv_w[r] = rsqrtf(ss);
    __nv_bfloat162* dst = reinterpret_cast<__nv_bfloat162*>(g_w_bf + (size_t)r * En);
    #pragma unroll
    for (int p = 0; p < 4; p++) {
        dst[(lane + p * 32) * 2]     = __floats2bfloat162_rn(v[p].x, v[p].y);
        dst[(lane + p * 32) * 2 + 1] = __floats2bfloat162_rn(v[p].z, v[p].w);
    }
}

// ------------------------- K1b: exact fp32 target logit --------------------
__global__ __launch_bounds__(256) void tgt_k(const float* __restrict__ emb,
                                             const float* __restrict__ w) {
    int warp = threadIdx.x >> 5, lane = threadIdx.x & 31;
    int b = blockIdx.x * 8 + warp;          // 64*8 = 512
    int lab = g_lab[b];
    const float4* e4 = reinterpret_cast<const float4*>(emb + (size_t)b * En);
    const float4* w4 = reinterpret_cast<const float4*>(w + (size_t)lab * En);
    float dot = 0.f;
    #pragma unroll
    for (int p = 0; p < 4; p++) {
        float4 a = e4[lane + p * 32];
        float4 c = w4[lane + p * 32];
        dot += a.x * c.x + a.y * c.y + a.z * c.z + a.w * c.w;
    }
    #pragma unroll
    for (int o = 16; o; o >>= 1) dot += __shfl_xor_sync(0xffffffffu, dot, o);
    if (lane == 0)
        g_tgt[b] = S_SCALE * dot * g_inv_e[b] * g_inv_w[lab] - SM_MARGIN;
}

// ------------------------- K2: bf16 GEMM + raw-exp softmax + centers copy --
__device__ __forceinline__ void mma16816(float* d, const uint32_t* a, const uint32_t* b) {
    asm volatile(
        "mma.sync.aligned.m16n8k16.row.col.f32.bf16.bf16.f32 "
        "{%0,%1,%2,%3}, {%4,%5,%6,%7}, {%8,%9}, {%0,%1,%2,%3};\n"
        : "+f"(d[0]), "+f"(d[1]), "+f"(d[2]), "+f"(d[3])
        : "r"(a[0]), "r"(a[1]), "r"(a[2]), "r"(a[3]), "r"(b[0]), "r"(b[1]));
}

// grid = (4, NTILES): x = m-tile (4 consecutive blocks share one B n-tile via L2)
__global__ __launch_bounds__(256, 2) void gemm_softmax_k(const float* __restrict__ centers,
                                                         float* __restrict__ outc) {
    extern __shared__ __align__(16) char dyn[];
    __nv_bfloat16* As = reinterpret_cast<__nv_bfloat16*>(dyn);            // [2][128][40]
    __nv_bfloat16* Bs = reinterpret_cast<__nv_bfloat16*>(dyn + 20480);    // [2][128][40]

    const int tid  = threadIdx.x;
    const int warp = tid >> 5, lane = tid & 31;
    const int wm = warp & 1, wn = warp >> 1;       // warps: 2 (M) x 4 (N)
    const int gid = lane >> 2, t4 = lane & 3;
    const int m0 = blockIdx.x * 128, n0 = blockIdx.y * 128;

    __shared__ int   s_lab[128];
    __shared__ float s_scl2[128];                  // S*inv_e*log2e per row
    __shared__ float s_invw[128];
    __shared__ float sm_s[4][128], sm_mx[4][128];

    if (tid < 128) {
        s_lab[tid]  = g_lab[m0 + tid];
        s_scl2[tid] = S_SCALE * LOG2E * g_inv_e[m0 + tid];
        int c = n0 + tid;
        s_invw[tid] = (c < Cn) ? g_inv_w[c] : 0.f;
    }

    float acc[4][4][4];
    #pragma unroll
    for (int a = 0; a < 4; a++)
        #pragma unroll
        for (int b = 0; b < 4; b++)
            #pragma unroll
            for (int c = 0; c < 4; c++) acc[a][b][c] = 0.f;

    auto load_stage = [&](int st, int kb) {
        #pragma unroll
        for (int i = 0; i < 2; i++) {
            int id  = tid + i * 256;
            int row = id >> 2, seg = id & 3;
            {   // A tile (embedding bf16)
                uint32_t dst = (uint32_t)__cvta_generic_to_shared(&As[(st * 128 + row) * 40 + seg * 8]);
                const void* src = &g_emb_bf[(size_t)(m0 + row) * En + kb + seg * 8];
                asm volatile("cp.async.cg.shared.global [%0], [%1], 16;\n" :: "r"(dst), "l"(src));
            }
            {   // B tile (weights bf16), clamp OOB rows (masked in epilogue)
                int gn = n0 + row;
                uint32_t dst = (uint32_t)__cvta_generic_to_shared(&Bs[(st * 128 + row) * 40 + seg * 8]);
                size_t gnc = (gn < Cn) ? (size_t)gn : (size_t)(Cn - 1);
                const void* src = &g_w_bf[gnc * En + kb + seg * 8];
                asm volatile("cp.async.cg.shared.global [%0], [%1], 16;\n" :: "r"(dst), "l"(src));
            }
        }
        asm volatile("cp.async.commit_group;\n");
    };

    load_stage(0, 0);
    load_stage(1, 32);

    // ---- hidden DRAM work: copy a slice of centers -> out (float2: outc is
    // only 8-byte aligned since out+2). Hidden under the bound mainloop. ----
    {
        int blk = blockIdx.y * 4 + blockIdx.x;     // 0..3127
        size_t base = (size_t)blk * CPY2_PER_BLK;
        const float2* src = reinterpret_cast<const float2*>(centers);
        float2* dst = reinterpret_cast<float2*>(outc);
        #pragma unroll 4
        for (int i = tid; i < CPY2_PER_BLK; i += 256) {
            size_t idx = base + i;
            if (idx < CPY2_TOTAL) dst[idx] = src[idx];
        }
    }

    #pragma unroll 1
    for (int ks = 0; ks < 16; ks++) {
        int st = ks & 1;
        if (ks < 15) asm volatile("cp.async.wait_group 1;\n");
        else         asm volatile("cp.async.wait_group 0;\n");
        __syncthreads();
        #pragma unroll
        for (int kk = 0; kk < 32; kk += 16) {
            uint32_t afr[4][4], bfr[4][2];
            #pragma unroll
            for (int mt = 0; mt < 4; mt++) {
                int r = wm * 64 + mt * 16 + gid;
                afr[mt][0] = *(const uint32_t*)&As[(st * 128 + r) * 40 + kk + t4 * 2];
                afr[mt][1] = *(const uint32_t*)&As[(st * 128 + r + 8) * 40 + kk + t4 * 2];
                afr[mt][2] = *(const uint32_t*)&As[(st * 128 + r) * 40 + kk + t4 * 2 + 8];
                afr[mt][3] = *(const uint32_t*)&As[(st * 128 + r + 8) * 40 + kk + t4 * 2 + 8];
            }
            #pragma unroll
            for (int nt = 0; nt < 4; nt++) {
                int c = wn * 32 + nt * 8 + gid;
                bfr[nt][0] = *(const uint32_t*)&Bs[(st * 128 + c) * 40 + kk + t4 * 2];
                bfr[nt][1] = *(const uint32_t*)&Bs[(st * 128 + c) * 40 + kk + t4 * 2 + 8];
            }
            #pragma unroll
            for (int mt = 0; mt < 4; mt++)
                #pragma unroll
                for (int nt = 0; nt < 4; nt++)
                    mma16816(acc[mt][nt], afr[mt], bfr[nt]);
        }
        __syncthreads();                       // retire all reads of stage st
        if (ks + 2 < 16) load_stage(st, (ks + 2) * 32);
    }

    // ---- epilogue: raw exp2 accumulation (no rescale), max for prec -------
    #pragma unroll
    for (int mt = 0; mt < 4; mt++) {
        #pragma unroll
        for (int h = 0; h < 2; h++) {
            int row  = wm * 64 + mt * 16 + gid + h * 8;
            int lab  = s_lab[row];
            float sc = s_scl2[row];
            float sr = 0.f, mx = -3.0e38f;
            #pragma unroll
            for (int nt = 0; nt < 4; nt++) {
                #pragma unroll
                for (int j = 0; j < 2; j++) {
                    int col = wn * 32 + nt * 8 + t4 * 2 + j;
                    int cg = n0 + col;
                    float l2 = acc[mt][nt][h * 2 + j] * sc * s_invw[col];
                    if (cg == lab) l2 -= M2_MARGIN;
                    if (cg >= Cn)  l2 = -1000.f;   // exp2 -> 0
                    mx = fmaxf(mx, l2);
                    sr += ex2(l2);
                }
            }
            #pragma unroll
            for (int o = 1; o <= 2; o <<= 1) {
                sr += __shfl_xor_sync(0xffffffffu, sr, o);
                mx = fmaxf(mx, __shfl_xor_sync(0xffffffffu, mx, o));
            }
            if (t4 == 0) { sm_s[wn][row] = sr; sm_mx[wn][row] = mx; }
        }
    }
    __syncthreads();
    if (tid < 128) {
        float s = sm_s[0][tid] + sm_s[1][tid] + sm_s[2][tid] + sm_s[3][tid];
        float m = fmaxf(fmaxf(sm_mx[0][tid], sm_mx[1][tid]),
                        fmaxf(sm_mx[2][tid], sm_mx[3][tid]));
        size_t o = (size_t)(m0 + tid) * NTILES + blockIdx.y;
        g_psum[o] = s; g_pmax[o] = m;
    }
}

// ------------------------- K3: per-row loss + prec reduce ------------------
__global__ void reduce_rows_k() {
    int gw = (blockIdx.x * blockDim.x + threadIdx.x) >> 5;  // warp per row
    int lane = threadIdx.x & 31;
    if (gw >= Bn) return;
    float s = 0.f, m = -3.0e38f;
    const float* ps = g_psum + (size_t)gw * NTILES;
    const float* pm = g_pmax + (size_t)gw * NTILES;
    for (int t = lane; t < NTILES; t += 32) {
        s += ps[t];
        m = fmaxf(m, pm[t]);
    }
    #pragma unroll
    for (int o = 16; o; o >>= 1) {
        s += __shfl_xor_sync(0xffffffffu, s, o);
        m = fmaxf(m, __shfl_xor_sync(0xffffffffu, m, o));
    }
    if (lane == 0) {
        g_rowloss[gw] = logf(s) - g_tgt[gw];
        g_correct[gw] = (g_tgt[gw] * LOG2E >= m) ? 1 : 0;
    }
}

// ------------------------- K4: scatter update + center loss (fused) --------
__global__ void scatter_closs_k(const float* __restrict__ emb,
                                const float* __restrict__ centers,
                                float* __restrict__ outc) {
    int b = blockIdx.x;
    int r = g_lab[b];
    float coef = ALPHA_C / (g_appear[b] + EPS_C);
    const float* e = emb + (size_t)b * En;
    const float* c = centers + (size_t)r * En;
    float* o = outc + (size_t)r * En;
    float ss = 0.f;
    for (int i = threadIdx.x; i < En; i += 128) {
        float d = e[i] - c[i];
        atomicAdd(&o[i], coef * d);
        ss += d * d;
    }
    #pragma unroll
    for (int of = 16; of; of >>= 1) ss += __shfl_xor_sync(0xffffffffu, ss, of);
    __shared__ float sp[4];
    int warp = threadIdx.x >> 5, lane = threadIdx.x & 31;
    if (lane == 0) sp[warp] = ss;
    __syncthreads();
    if (threadIdx.x == 0)
        atomicAdd(&g_closs, sp[0] + sp[1] + sp[2] + sp[3]);
}

// ------------------------- K5: finalize scalars ----------------------------
__global__ void finalize_k(float* __restrict__ out) {
    int tid = threadIdx.x;  // 512
    float sl = g_rowloss[tid];
    int   sc = g_correct[tid];
    #pragma unroll
    for (int o = 16; o; o >>= 1) {
        sl += __shfl_xor_sync(0xffffffffu, sl, o);
        sc += __shfl_xor_sync(0xffffffffu, sc, o);
    }
    __shared__ float sm_l[16];
    __shared__ int   sm_c[16];
    if ((tid & 31) == 0) { sm_l[tid >> 5] = sl; sm_c[tid >> 5] = sc; }
    __syncthreads();
    if (tid == 0) {
        float L = 0.f; int Cc = 0;
        #pragma unroll
        for (int i = 0; i < 16; i++) { L += sm_l[i]; Cc += sm_c[i]; }
        out[0] = 100.0f * (float)Cc / (float)Bn;
        out[1] = L / (float)Bn + LAMDA * (g_closs / (float)(Bn * En));
    }
}

// ------------------------- launcher ---------------------------------------
extern "C" void kernel_launch(void* const* d_in, const int* in_sizes, int n_in,
                              void* d_out, int out_size) {
    (void)in_sizes; (void)n_in; (void)out_size;
    const float* emb = (const float*)d_in[0];
    const float* w   = (const float*)d_in[1];
    const float* cen = (const float*)d_in[2];
    const void*  lab = d_in[3];
    float* out = (float*)d_out;

    cudaFuncSetAttribute(gemm_softmax_k,
                         cudaFuncAttributeMaxDynamicSharedMemorySize, SMEM_DYN);

    decode_labels_k<<<1, 256>>>(lab);
    prep_emb_k<<<Bn, 128>>>(emb);
    appear_k<<<1, Bn>>>();
    prep_w_k<<<Cn / 8, 256>>>(w);
    tgt_k<<<Bn / 8, 256>>>(emb, w);
    gemm_softmax_k<<<dim3(4, NTILES), 256, SMEM_DYN>>>(cen, out + 2);
    reduce_rows_k<<<64, 256>>>();
    scatter_closs_k<<<Bn, 128>>>(emb, cen, out + 2);
    finalize_k<<<1, Bn>>>(out);
}

// round 15
// speedup vs baseline: 1.5759x; 1.2566x over previous
#include <cuda_runtime.h>
#include <cuda_bf16.h>
#include <cuda_fp16.h>
#include <math.h>
#include <stdint.h>

// Problem constants
#define Bn 512
#define En 512
#define Cn 100000
#define NTILES 782            // ceil(100000/128)
#define S_SCALE 30.0f
#define SM_MARGIN 10.5f       // S*M
#define LAMDA 0.01f
#define ALPHA_C 0.5f
#define EPS_C 1e-6f
#define LOG2E 1.4426950408889634f
#define LN2F 0.6931471805599453f
#define M2_MARGIN (10.5f * 1.4426950408889634f)   // margin in log2 units
#define NEGBIG -3.0e38f

#define SMEM_DYN (2 * 128 * 40 * 2 * 2)           // As+Bs double-buffered = 40960 B

// ------------------------- device scratch (static, no allocation) ----------
__device__ int   g_lab[Bn];
__device__ float g_inv_e[Bn];
__device__ __nv_bfloat16 g_emb_bf[Bn * En];
__device__ float g_inv_w[Cn];
__device__ __nv_bfloat16 g_w_bf[(size_t)Cn * En];
__device__ float g_tgt[Bn];
__device__ float g_psum[(size_t)Bn * NTILES];     // tile sumexp2 (biased by tile max)
__device__ float g_pmax[(size_t)Bn * NTILES];     // tile max (log2 units, margined)
__device__ float g_rowloss[Bn];
__device__ int   g_correct[Bn];
__device__ float g_closs;
__device__ float g_appear[Bn];

__device__ __forceinline__ float ex2f(float x) {
    float r;
    asm("ex2.approx.f32 %0, %1;" : "=f"(r) : "f"(x));
    return r;
}

// ------------------------- K-1: decode labels (int32 vs int64 autodetect) --
__global__ void decode_labels_k(const void* __restrict__ labraw) {
    const long long* l64 = (const long long*)labraw;
    const int*       l32 = (const int*)labraw;
    int t = threadIdx.x;               // 256 threads
    long long v = l64[t];              // first 2048 bytes: safe in both layouts
    int valid = (v >= 0 && v < (long long)Cn) ? 1 : 0;
    #pragma unroll
    for (int o = 16; o; o >>= 1) valid &= __shfl_xor_sync(0xffffffffu, valid, o);
    __shared__ int sv[8];
    if ((t & 31) == 0) sv[t >> 5] = valid;
    __syncthreads();
    int all64 = sv[0] & sv[1] & sv[2] & sv[3] & sv[4] & sv[5] & sv[6] & sv[7];
    if (all64) {
        g_lab[t]       = (int)l64[t];
        g_lab[t + 256] = (int)l64[t + 256];
    } else {
        g_lab[t]       = l32[t];
        g_lab[t + 256] = l32[t + 256];
    }
}

// ------------------------- K0: embedding norms + bf16 ----------------------
__global__ void prep_emb_k(const float* __restrict__ emb) {
    int b = blockIdx.x;            // 512 blocks
    int t = threadIdx.x;           // 128 threads
    float4 v = reinterpret_cast<const float4*>(emb + (size_t)b * En)[t];
    float ss = v.x * v.x + v.y * v.y + v.z * v.z + v.w * v.w;
    #pragma unroll
    for (int o = 16; o; o >>= 1) ss += __shfl_xor_sync(0xffffffffu, ss, o);
    __shared__ float sp[4];
    if ((t & 31) == 0) sp[t >> 5] = ss;
    __syncthreads();
    if (t == 0) {
        g_inv_e[b] = rsqrtf(sp[0] + sp[1] + sp[2] + sp[3]);
        if (b == 0) g_closs = 0.0f;
    }
    __nv_bfloat162* dst = reinterpret_cast<__nv_bfloat162*>(g_emb_bf + (size_t)b * En);
    dst[t * 2]     = __floats2bfloat162_rn(v.x, v.y);
    dst[t * 2 + 1] = __floats2bfloat162_rn(v.z, v.w);
}

// ------------------------- K0b: appear counts ------------------------------
__global__ void appear_k() {
    __shared__ int labs[Bn];
    int t = threadIdx.x;
    labs[t] = g_lab[t];
    __syncthreads();
    int mine = labs[t], cnt = 0;
    #pragma unroll 8
    for (int i = 0; i < Bn; i++) cnt += (labs[i] == mine);
    g_appear[t] = (float)cnt;
}

// ------------------------- K1: weight norms + bf16 (warp per row) ----------
__global__ __launch_bounds__(256) void prep_w_k(const float* __restrict__ w) {
    int warp = threadIdx.x >> 5, lane = threadIdx.x & 31;
    int r = blockIdx.x * 8 + warp;          // 12500*8 = 100000 exactly
    const float4* src = reinterpret_cast<const float4*>(w + (size_t)r * En);
    float4 v[4];
    float ss = 0.f;
    #pragma unroll
    for (int p = 0; p < 4; p++) {
        v[p] = src[lane + p * 32];
        ss += v[p].x * v[p].x + v[p].y * v[p].y + v[p].z * v[p].z + v[p].w * v[p].w;
    }
    #pragma unroll
    for (int o = 16; o; o >>= 1) ss += __shfl_xor_sync(0xffffffffu, ss, o);
    if (lane == 0) g_inv_w[r] = rsqrtf(ss);
    __nv_bfloat162* dst = reinterpret_cast<__nv_bfloat162*>(g_w_bf + (size_t)r * En);
    #pragma unroll
    for (int p = 0; p < 4; p++) {
        dst[(lane + p * 32) * 2]     = __floats2bfloat162_rn(v[p].x, v[p].y);
        dst[(lane + p * 32) * 2 + 1] = __floats2bfloat162_rn(v[p].z, v[p].w);
    }
}

// ------------------------- K1b: exact fp32 target logit --------------------
__global__ __launch_bounds__(256) void tgt_k(const float* __restrict__ emb,
                                             const float* __restrict__ w) {
    int warp = threadIdx.x >> 5, lane = threadIdx.x & 31;
    int b = blockIdx.x * 8 + warp;          // 64*8 = 512
    int lab = g_lab[b];
    const float4* e4 = reinterpret_cast<const float4*>(emb + (size_t)b * En);
    const float4* w4 = reinterpret_cast<const float4*>(w + (size_t)lab * En);
    float dot = 0.f;
    #pragma unroll
    for (int p = 0; p < 4; p++) {
        float4 a = e4[lane + p * 32];
        float4 c = w4[lane + p * 32];
        dot += a.x * c.x + a.y * c.y + a.z * c.z + a.w * c.w;
    }
    #pragma unroll
    for (int o = 16; o; o >>= 1) dot += __shfl_xor_sync(0xffffffffu, dot, o);
    if (lane == 0)
        g_tgt[b] = S_SCALE * dot * g_inv_e[b] * g_inv_w[lab] - SM_MARGIN;
}

// ------------------------- K2: bf16 GEMM + f16x2-exp softmax partials ------
__device__ __forceinline__ void mma16816(float* d, const uint32_t* a, const uint32_t* b) {
    asm volatile(
        "mma.sync.aligned.m16n8k16.row.col.f32.bf16.bf16.f32 "
        "{%0,%1,%2,%3}, {%4,%5,%6,%7}, {%8,%9}, {%0,%1,%2,%3};\n"
        : "+f"(d[0]), "+f"(d[1]), "+f"(d[2]), "+f"(d[3])
        : "r"(a[0]), "r"(a[1]), "r"(a[2]), "r"(a[3]), "r"(b[0]), "r"(b[1]));
}

// grid = (4, NTILES): x = m-tile (4 consecutive blocks share one B n-tile via L2)
__global__ __launch_bounds__(256, 2) void gemm_softmax_k() {
    extern __shared__ __align__(16) char dyn[];
    __nv_bfloat16* As = reinterpret_cast<__nv_bfloat16*>(dyn);            // [2][128][40]
    __nv_bfloat16* Bs = reinterpret_cast<__nv_bfloat16*>(dyn + 20480);    // [2][128][40]

    const int tid  = threadIdx.x;
    const int warp = tid >> 5, lane = tid & 31;
    const int wm = warp & 1, wn = warp >> 1;       // warps: 2 (M) x 4 (N)
    const int gid = lane >> 2, t4 = lane & 3;
    const int m0 = blockIdx.x * 128, n0 = blockIdx.y * 128;

    __shared__ int   s_lab[128];
    __shared__ float s_scl2[128];                  // S*inv_e*log2e per row
    __shared__ float s_invw[128];
    __shared__ float sm_s[4][128], sm_mx[4][128];

    if (tid < 128) {
        s_lab[tid]  = g_lab[m0 + tid];
        s_scl2[tid] = S_SCALE * LOG2E * g_inv_e[m0 + tid];
        int c = n0 + tid;
        s_invw[tid] = (c < Cn) ? g_inv_w[c] : 0.f;
    }

    float acc[4][4][4];
    #pragma unroll
    for (int a = 0; a < 4; a++)
        #pragma unroll
        for (int b = 0; b < 4; b++)
            #pragma unroll
            for (int c = 0; c < 4; c++) acc[a][b][c] = 0.f;

    auto load_stage = [&](int st, int kb) {
        #pragma unroll
        for (int i = 0; i < 2; i++) {
            int id  = tid + i * 256;
            int row = id >> 2, seg = id & 3;
            {   // A tile (embedding bf16)
                uint32_t dst = (uint32_t)__cvta_generic_to_shared(&As[(st * 128 + row) * 40 + seg * 8]);
                const void* src = &g_emb_bf[(size_t)(m0 + row) * En + kb + seg * 8];
                asm volatile("cp.async.cg.shared.global [%0], [%1], 16;\n" :: "r"(dst), "l"(src));
            }
            {   // B tile (weights bf16), clamp OOB rows (masked in epilogue)
                int gn = n0 + row;
                uint32_t dst = (uint32_t)__cvta_generic_to_shared(&Bs[(st * 128 + row) * 40 + seg * 8]);
                size_t gnc = (gn < Cn) ? (size_t)gn : (size_t)(Cn - 1);
                const void* src = &g_w_bf[gnc * En + kb + seg * 8];
                asm volatile("cp.async.cg.shared.global [%0], [%1], 16;\n" :: "r"(dst), "l"(src));
            }
        }
        asm volatile("cp.async.commit_group;\n");
    };

    load_stage(0, 0);
    load_stage(1, 32);
    #pragma unroll 1
    for (int ks = 0; ks < 16; ks++) {
        int st = ks & 1;
        if (ks < 15) asm volatile("cp.async.wait_group 1;\n");
        else         asm volatile("cp.async.wait_group 0;\n");
        __syncthreads();
        #pragma unroll
        for (int kk = 0; kk < 32; kk += 16) {
            uint32_t afr[4][4], bfr[4][2];
            #pragma unroll
            for (int mt = 0; mt < 4; mt++) {
                int r = wm * 64 + mt * 16 + gid;
                afr[mt][0] = *(const uint32_t*)&As[(st * 128 + r) * 40 + kk + t4 * 2];
                afr[mt][1] = *(const uint32_t*)&As[(st * 128 + r + 8) * 40 + kk + t4 * 2];
                afr[mt][2] = *(const uint32_t*)&As[(st * 128 + r) * 40 + kk + t4 * 2 + 8];
                afr[mt][3] = *(const uint32_t*)&As[(st * 128 + r + 8) * 40 + kk + t4 * 2 + 8];
            }
            #pragma unroll
            for (int nt = 0; nt < 4; nt++) {
                int c = wn * 32 + nt * 8 + gid;
                bfr[nt][0] = *(const uint32_t*)&Bs[(st * 128 + c) * 40 + kk + t4 * 2];
                bfr[nt][1] = *(const uint32_t*)&Bs[(st * 128 + c) * 40 + kk + t4 * 2 + 8];
            }
            #pragma unroll
            for (int mt = 0; mt < 4; mt++)
                #pragma unroll
                for (int nt = 0; nt < 4; nt++)
                    mma16816(acc[mt][nt], afr[mt], bfr[nt]);
        }
        __syncthreads();                       // retire all reads of stage st
        if (ks + 2 < 16) load_stage(st, (ks + 2) * 32);
    }

    // ---- epilogue: quad-max bias + f16x2 exp2 (2 exps / MUFU op) ----------
    #pragma unroll
    for (int mt = 0; mt < 4; mt++) {
        #pragma unroll
        for (int h = 0; h < 2; h++) {
            int row  = wm * 64 + mt * 16 + gid + h * 8;
            int lab  = s_lab[row];
            float sc = s_scl2[row];
            float f[8];
            float mx = NEGBIG;
            #pragma unroll
            for (int nt = 0; nt < 4; nt++) {
                #pragma unroll
                for (int j = 0; j < 2; j++) {
                    int col = wn * 32 + nt * 8 + t4 * 2 + j;
                    int cg = n0 + col;
                    float l2 = acc[mt][nt][h * 2 + j] * sc * s_invw[col];
                    if (cg == lab) l2 -= M2_MARGIN;
                    if (cg >= Cn)  l2 = NEGBIG;
                    f[nt * 2 + j] = l2;
                    mx = fmaxf(mx, l2);
                }
            }
            // common bias across the 4-lane quad (true 32-col max, for prec too)
            float qm = mx;
            qm = fmaxf(qm, __shfl_xor_sync(0xffffffffu, qm, 1));
            qm = fmaxf(qm, __shfl_xor_sync(0xffffffffu, qm, 2));
            uint32_t acc2 = 0;                 // half2 accumulator
            #pragma unroll
            for (int p = 0; p < 4; p++) {
                uint32_t hh, rr;
                float a0 = f[2 * p] - qm, a1 = f[2 * p + 1] - qm;
                asm("cvt.rn.f16x2.f32 %0, %1, %2;" : "=r"(hh) : "f"(a1), "f"(a0));
                asm("ex2.approx.f16x2 %0, %1;" : "=r"(rr) : "r"(hh));
                asm("add.rn.f16x2 %0, %1, %2;" : "=r"(acc2) : "r"(acc2), "r"(rr));
            }
            __half2 h2 = *reinterpret_cast<__half2*>(&acc2);
            float sr = __low2float(h2) + __high2float(h2);
            sr += __shfl_xor_sync(0xffffffffu, sr, 1);
            sr += __shfl_xor_sync(0xffffffffu, sr, 2);
            if (t4 == 0) { sm_s[wn][row] = sr; sm_mx[wn][row] = qm; }
        }
    }
    __syncthreads();
    if (tid < 128) {
        // combine 4 n-quadrant partials with log2-domain rescale
        float m = sm_mx[0][tid], s = sm_s[0][tid];
        #pragma unroll
        for (int wq = 1; wq < 4; wq++) {
            float mw = sm_mx[wq][tid], sw = sm_s[wq][tid];
            float M = fmaxf(m, mw);
            s = s * ex2f(m - M) + sw * ex2f(mw - M);
            m = M;
        }
        size_t o = (size_t)(m0 + tid) * NTILES + blockIdx.y;
        g_psum[o] = s; g_pmax[o] = m;
    }
}

// ------------------------- K3: per-row loss + prec reduce ------------------
__global__ void reduce_rows_k() {
    int gw = (blockIdx.x * blockDim.x + threadIdx.x) >> 5;  // warp per row
    int lane = threadIdx.x & 31;
    if (gw >= Bn) return;
    float M = NEGBIG, S = 0.f;
    const float* ps = g_psum + (size_t)gw * NTILES;
    const float* pm = g_pmax + (size_t)gw * NTILES;
    for (int t = lane; t < NTILES; t += 32) {
        float mt = pm[t], st = ps[t];
        if (mt > M) { S = S * ex2f(M - mt) + st; M = mt; }
        else        { S += st * ex2f(mt - M); }
    }
    #pragma unroll
    for (int o = 16; o; o >>= 1) {
        float m2 = __shfl_xor_sync(0xffffffffu, M, o);
        float s2 = __shfl_xor_sync(0xffffffffu, S, o);
        float Mn = fmaxf(M, m2);
        S = S * ex2f(M - Mn) + s2 * ex2f(m2 - Mn);
        M = Mn;
    }
    if (lane == 0) {
        g_rowloss[gw] = LN2F * (M + __log2f(S)) - g_tgt[gw];
        g_correct[gw] = (g_tgt[gw] * LOG2E >= M) ? 1 : 0;
    }
}

// ------------------------- K4: copy centers -> out -------------------------
__global__ void copy_centers_k(const float* __restrict__ centers, float* __restrict__ out) {
    size_t i = (size_t)blockIdx.x * blockDim.x + threadIdx.x;   // float2 index
    const float2* src = reinterpret_cast<const float2*>(centers);
    float2* dst = reinterpret_cast<float2*>(out);
    dst[i] = src[i];
}

// ------------------------- K5: scatter update + center loss (fused) --------
__global__ void scatter_closs_k(const float* __restrict__ emb,
                                const float* __restrict__ centers,
                                float* __restrict__ outc) {
    int b = blockIdx.x;
    int r = g_lab[b];
    float coef = ALPHA_C / (g_appear[b] + EPS_C);
    const float* e = emb + (size_t)b * En;
    const float* c = centers + (size_t)r * En;
    float* o = outc + (size_t)r * En;
    float ss = 0.f;
    for (int i = threadIdx.x; i < En; i += 128) {
        float d = e[i] - c[i];
        atomicAdd(&o[i], coef * d);
        ss += d * d;
    }
    #pragma unroll
    for (int of = 16; of; of >>= 1) ss += __shfl_xor_sync(0xffffffffu, ss, of);
    __shared__ float sp[4];
    int warp = threadIdx.x >> 5, lane = threadIdx.x & 31;
    if (lane == 0) sp[warp] = ss;
    __syncthreads();
    if (threadIdx.x == 0)
        atomicAdd(&g_closs, sp[0] + sp[1] + sp[2] + sp[3]);
}

// ------------------------- K6: finalize scalars ----------------------------
__global__ void finalize_k(float* __restrict__ out) {
    int tid = threadIdx.x;  // 512
    float sl = g_rowloss[tid];
    int   sc = g_correct[tid];
    #pragma unroll
    for (int o = 16; o; o >>= 1) {
        sl += __shfl_xor_sync(0xffffffffu, sl, o);
        sc += __shfl_xor_sync(0xffffffffu, sc, o);
    }
    __shared__ float sm_l[16];
    __shared__ int   sm_c[16];
    if ((tid & 31) == 0) { sm_l[tid >> 5] = sl; sm_c[tid >> 5] = sc; }
    __syncthreads();
    if (tid == 0) {
        float L = 0.f; int Cc = 0;
        #pragma unroll
        for (int i = 0; i < 16; i++) { L += sm_l[i]; Cc += sm_c[i]; }
        out[0] = 100.0f * (float)Cc / (float)Bn;
        out[1] = L / (float)Bn + LAMDA * (g_closs / (float)(Bn * En));
    }
}

// ------------------------- launcher ---------------------------------------
extern "C" void kernel_launch(void* const* d_in, const int* in_sizes, int n_in,
                              void* d_out, int out_size) {
    (void)in_sizes; (void)n_in; (void)out_size;
    const float* emb = (const float*)d_in[0];
    const float* w   = (const float*)d_in[1];
    const float* cen = (const float*)d_in[2];
    const void*  lab = d_in[3];
    float* out = (float*)d_out;

    cudaFuncSetAttribute(gemm_softmax_k,
                         cudaFuncAttributeMaxDynamicSharedMemorySize, SMEM_DYN);

    // Order chosen so gemm_softmax_k is user-launch #3 (ncu -s 5 capture slot).
    decode_labels_k<<<1, 256>>>(lab);
    prep_emb_k<<<Bn, 128>>>(emb);
    prep_w_k<<<Cn / 8, 256>>>(w);
    gemm_softmax_k<<<dim3(4, NTILES), 256, SMEM_DYN>>>();
    copy_centers_k<<<100000, 256>>>(cen, out + 2);
    tgt_k<<<Bn / 8, 256>>>(emb, w);
    appear_k<<<1, Bn>>>();
    reduce_rows_k<<<64, 256>>>();
    scatter_closs_k<<<Bn, 128>>>(emb, cen, out + 2);
    finalize_k<<<1, Bn>>>(out);
}

// round 16
// speedup vs baseline: 1.6866x; 1.0703x over previous
#include <cuda_runtime.h>
#include <cuda_bf16.h>
#include <cuda_fp16.h>
#include <math.h>
#include <stdint.h>

// Problem constants
#define Bn 512
#define En 512
#define Cn 100000
#define NTILES 782            // ceil(100000/128)
#define S_SCALE 30.0f
#define SM_MARGIN 10.5f       // S*M
#define LAMDA 0.01f
#define ALPHA_C 0.5f
#define EPS_C 1e-6f
#define LOG2E 1.4426950408889634f
#define LN2F 0.6931471805599453f
#define M2_MARGIN (10.5f * 1.4426950408889634f)   // margin in log2 units
#define NEGBIG -3.0e38f

#define SMEM_DYN (2 * 128 * 40 * 2 * 2)           // As+Bs double-buffered = 40960 B

// ------------------------- device scratch (static, no allocation) ----------
__device__ int   g_lab[Bn];
__device__ float g_inv_e[Bn];
__device__ __nv_bfloat16 g_emb_bf[Bn * En];
__device__ float g_inv_w[Cn];
__device__ __nv_bfloat16 g_w_bf[(size_t)Cn * En];
__device__ float g_tgt[Bn];
__device__ float g_psum[(size_t)Bn * NTILES];     // tile sumexp2 (biased by tile max)
__device__ float g_pmax[(size_t)Bn * NTILES];     // tile max (log2 units, margined)
__device__ float g_rowloss[Bn];
__device__ int   g_correct[Bn];
__device__ float g_closs;
__device__ float g_appear[Bn];

__device__ __forceinline__ float ex2f(float x) {
    float r;
    asm("ex2.approx.f32 %0, %1;" : "=f"(r) : "f"(x));
    return r;
}

// ------------------------- K-1: decode labels (int32 vs int64 autodetect) --
__global__ void decode_labels_k(const void* __restrict__ labraw) {
    const long long* l64 = (const long long*)labraw;
    const int*       l32 = (const int*)labraw;
    int t = threadIdx.x;               // 256 threads
    long long v = l64[t];              // first 2048 bytes: safe in both layouts
    int valid = (v >= 0 && v < (long long)Cn) ? 1 : 0;
    #pragma unroll
    for (int o = 16; o; o >>= 1) valid &= __shfl_xor_sync(0xffffffffu, valid, o);
    __shared__ int sv[8];
    if ((t & 31) == 0) sv[t >> 5] = valid;
    __syncthreads();
    int all64 = sv[0] & sv[1] & sv[2] & sv[3] & sv[4] & sv[5] & sv[6] & sv[7];
    if (all64) {
        g_lab[t]       = (int)l64[t];
        g_lab[t + 256] = (int)l64[t + 256];
    } else {
        g_lab[t]       = l32[t];
        g_lab[t + 256] = l32[t + 256];
    }
    if (t == 0) g_closs = 0.0f;        // zero BEFORE the stream fork (scatter adds to it)
}

// ------------------------- K0: embedding norms + bf16 ----------------------
__global__ void prep_emb_k(const float* __restrict__ emb) {
    int b = blockIdx.x;            // 512 blocks
    int t = threadIdx.x;           // 128 threads
    float4 v = reinterpret_cast<const float4*>(emb + (size_t)b * En)[t];
    float ss = v.x * v.x + v.y * v.y + v.z * v.z + v.w * v.w;
    #pragma unroll
    for (int o = 16; o; o >>= 1) ss += __shfl_xor_sync(0xffffffffu, ss, o);
    __shared__ float sp[4];
    if ((t & 31) == 0) sp[t >> 5] = ss;
    __syncthreads();
    if (t == 0) g_inv_e[b] = rsqrtf(sp[0] + sp[1] + sp[2] + sp[3]);
    __nv_bfloat162* dst = reinterpret_cast<__nv_bfloat162*>(g_emb_bf + (size_t)b * En);
    dst[t * 2]     = __floats2bfloat162_rn(v.x, v.y);
    dst[t * 2 + 1] = __floats2bfloat162_rn(v.z, v.w);
}

// ------------------------- K0b: appear counts ------------------------------
__global__ void appear_k() {
    __shared__ int labs[Bn];
    int t = threadIdx.x;
    labs[t] = g_lab[t];
    __syncthreads();
    int mine = labs[t], cnt = 0;
    #pragma unroll 8
    for (int i = 0; i < Bn; i++) cnt += (labs[i] == mine);
    g_appear[t] = (float)cnt;
}

// ------------------------- K1: weight norms + bf16 (warp per row) ----------
__global__ __launch_bounds__(256) void prep_w_k(const float* __restrict__ w) {
    int warp = threadIdx.x >> 5, lane = threadIdx.x & 31;
    int r = blockIdx.x * 8 + warp;          // 12500*8 = 100000 exactly
    const float4* src = reinterpret_cast<const float4*>(w + (size_t)r * En);
    float4 v[4];
    float ss = 0.f;
    #pragma unroll
    for (int p = 0; p < 4; p++) {
        v[p] = src[lane + p * 32];
        ss += v[p].x * v[p].x + v[p].y * v[p].y + v[p].z * v[p].z + v[p].w * v[p].w;
    }
    #pragma unroll
    for (int o = 16; o; o >>= 1) ss += __shfl_xor_sync(0xffffffffu, ss, o);
    if (lane == 0) g_inv_w[r] = rsqrtf(ss);
    __nv_bfloat162* dst = reinterpret_cast<__nv_bfloat162*>(g_w_bf + (size_t)r * En);
    #pragma unroll
    for (int p = 0; p < 4; p++) {
        dst[(lane + p * 32) * 2]     = __floats2bfloat162_rn(v[p].x, v[p].y);
        dst[(lane + p * 32) * 2 + 1] = __floats2bfloat162_rn(v[p].z, v[p].w);
    }
}

// ------------------------- K1b: exact fp32 target logit --------------------
__global__ __launch_bounds__(256) void tgt_k(const float* __restrict__ emb,
                                             const float* __restrict__ w) {
    int warp = threadIdx.x >> 5, lane = threadIdx.x & 31;
    int b = blockIdx.x * 8 + warp;          // 64*8 = 512
    int lab = g_lab[b];
    const float4* e4 = reinterpret_cast<const float4*>(emb + (size_t)b * En);
    const float4* w4 = reinterpret_cast<const float4*>(w + (size_t)lab * En);
    float dot = 0.f;
    #pragma unroll
    for (int p = 0; p < 4; p++) {
        float4 a = e4[lane + p * 32];
        float4 c = w4[lane + p * 32];
        dot += a.x * c.x + a.y * c.y + a.z * c.z + a.w * c.w;
    }
    #pragma unroll
    for (int o = 16; o; o >>= 1) dot += __shfl_xor_sync(0xffffffffu, dot, o);
    if (lane == 0)
        g_tgt[b] = S_SCALE * dot * g_inv_e[b] * g_inv_w[lab] - SM_MARGIN;
}

// ------------------------- K2: bf16 GEMM + f16x2-exp softmax partials ------
__device__ __forceinline__ void mma16816(float* d, const uint32_t* a, const uint32_t* b) {
    asm volatile(
        "mma.sync.aligned.m16n8k16.row.col.f32.bf16.bf16.f32 "
        "{%0,%1,%2,%3}, {%4,%5,%6,%7}, {%8,%9}, {%0,%1,%2,%3};\n"
        : "+f"(d[0]), "+f"(d[1]), "+f"(d[2]), "+f"(d[3])
        : "r"(a[0]), "r"(a[1]), "r"(a[2]), "r"(a[3]), "r"(b[0]), "r"(b[1]));
}

// grid = (4, NTILES): x = m-tile (4 consecutive blocks share one B n-tile via L2)
__global__ __launch_bounds__(256, 2) void gemm_softmax_k() {
    extern __shared__ __align__(16) char dyn[];
    __nv_bfloat16* As = reinterpret_cast<__nv_bfloat16*>(dyn);            // [2][128][40]
    __nv_bfloat16* Bs = reinterpret_cast<__nv_bfloat16*>(dyn + 20480);    // [2][128][40]

    const int tid  = threadIdx.x;
    const int warp = tid >> 5, lane = tid & 31;
    const int wm = warp & 1, wn = warp >> 1;       // warps: 2 (M) x 4 (N)
    const int gid = lane >> 2, t4 = lane & 3;
    const int m0 = blockIdx.x * 128, n0 = blockIdx.y * 128;

    __shared__ int   s_lab[128];
    __shared__ float s_scl2[128];                  // S*inv_e*log2e per row
    __shared__ float s_invw[128];
    __shared__ float sm_s[4][128], sm_mx[4][128];

    if (tid < 128) {
        s_lab[tid]  = g_lab[m0 + tid];
        s_scl2[tid] = S_SCALE * LOG2E * g_inv_e[m0 + tid];
        int c = n0 + tid;
        s_invw[tid] = (c < Cn) ? g_inv_w[c] : 0.f;
    }

    float acc[4][4][4];
    #pragma unroll
    for (int a = 0; a < 4; a++)
        #pragma unroll
        for (int b = 0; b < 4; b++)
            #pragma unroll
            for (int c = 0; c < 4; c++) acc[a][b][c] = 0.f;

    auto load_stage = [&](int st, int kb) {
        #pragma unroll
        for (int i = 0; i < 2; i++) {
            int id  = tid + i * 256;
            int row = id >> 2, seg = id & 3;
            {   // A tile (embedding bf16)
                uint32_t dst = (uint32_t)__cvta_generic_to_shared(&As[(st * 128 + row) * 40 + seg * 8]);
                const void* src = &g_emb_bf[(size_t)(m0 + row) * En + kb + seg * 8];
                asm volatile("cp.async.cg.shared.global [%0], [%1], 16;\n" :: "r"(dst), "l"(src));
            }
            {   // B tile (weights bf16), clamp OOB rows (masked in epilogue)
                int gn = n0 + row;
                uint32_t dst = (uint32_t)__cvta_generic_to_shared(&Bs[(st * 128 + row) * 40 + seg * 8]);
                size_t gnc = (gn < Cn) ? (size_t)gn : (size_t)(Cn - 1);
                const void* src = &g_w_bf[gnc * En + kb + seg * 8];
                asm volatile("cp.async.cg.shared.global [%0], [%1], 16;\n" :: "r"(dst), "l"(src));
            }
        }
        asm volatile("cp.async.commit_group;\n");
    };

    load_stage(0, 0);
    load_stage(1, 32);
    #pragma unroll 1
    for (int ks = 0; ks < 16; ks++) {
        int st = ks & 1;
        if (ks < 15) asm volatile("cp.async.wait_group 1;\n");
        else         asm volatile("cp.async.wait_group 0;\n");
        __syncthreads();
        #pragma unroll
        for (int kk = 0; kk < 32; kk += 16) {
            uint32_t afr[4][4], bfr[4][2];
            #pragma unroll
            for (int mt = 0; mt < 4; mt++) {
                int r = wm * 64 + mt * 16 + gid;
                afr[mt][0] = *(const uint32_t*)&As[(st * 128 + r) * 40 + kk + t4 * 2];
                afr[mt][1] = *(const uint32_t*)&As[(st * 128 + r + 8) * 40 + kk + t4 * 2];
                afr[mt][2] = *(const uint32_t*)&As[(st * 128 + r) * 40 + kk + t4 * 2 + 8];
                afr[mt][3] = *(const uint32_t*)&As[(st * 128 + r + 8) * 40 + kk + t4 * 2 + 8];
            }
            #pragma unroll
            for (int nt = 0; nt < 4; nt++) {
                int c = wn * 32 + nt * 8 + gid;
                bfr[nt][0] = *(const uint32_t*)&Bs[(st * 128 + c) * 40 + kk + t4 * 2];
                bfr[nt][1] = *(const uint32_t*)&Bs[(st * 128 + c) * 40 + kk + t4 * 2 + 8];
            }
            #pragma unroll
            for (int mt = 0; mt < 4; mt++)
                #pragma unroll
                for (int nt = 0; nt < 4; nt++)
                    mma16816(acc[mt][nt], afr[mt], bfr[nt]);
        }
        __syncthreads();                       // retire all reads of stage st
        if (ks + 2 < 16) load_stage(st, (ks + 2) * 32);
    }

    // ---- epilogue: quad-max bias + f16x2 exp2 (2 exps / MUFU op) ----------
    #pragma unroll
    for (int mt = 0; mt < 4; mt++) {
        #pragma unroll
        for (int h = 0; h < 2; h++) {
            int row  = wm * 64 + mt * 16 + gid + h * 8;
            int lab  = s_lab[row];
            float sc = s_scl2[row];
            float f[8];
            float mx = NEGBIG;
            #pragma unroll
            for (int nt = 0; nt < 4; nt++) {
                #pragma unroll
                for (int j = 0; j < 2; j++) {
                    int col = wn * 32 + nt * 8 + t4 * 2 + j;
                    int cg = n0 + col;
                    float l2 = acc[mt][nt][h * 2 + j] * sc * s_invw[col];
                    if (cg == lab) l2 -= M2_MARGIN;
                    if (cg >= Cn)  l2 = NEGBIG;
                    f[nt * 2 + j] = l2;
                    mx = fmaxf(mx, l2);
                }
            }
            // common bias across the 4-lane quad (true 32-col max, for prec too)
            float qm = mx;
            qm = fmaxf(qm, __shfl_xor_sync(0xffffffffu, qm, 1));
            qm = fmaxf(qm, __shfl_xor_sync(0xffffffffu, qm, 2));
            uint32_t acc2 = 0;                 // half2 accumulator
            #pragma unroll
            for (int p = 0; p < 4; p++) {
                uint32_t hh, rr;
                float a0 = f[2 * p] - qm, a1 = f[2 * p + 1] - qm;
                asm("cvt.rn.f16x2.f32 %0, %1, %2;" : "=r"(hh) : "f"(a1), "f"(a0));
                asm("ex2.approx.f16x2 %0, %1;" : "=r"(rr) : "r"(hh));
                asm("add.rn.f16x2 %0, %1, %2;" : "=r"(acc2) : "r"(acc2), "r"(rr));
            }
            __half2 h2 = *reinterpret_cast<__half2*>(&acc2);
            float sr = __low2float(h2) + __high2float(h2);
            sr += __shfl_xor_sync(0xffffffffu, sr, 1);
            sr += __shfl_xor_sync(0xffffffffu, sr, 2);
            if (t4 == 0) { sm_s[wn][row] = sr; sm_mx[wn][row] = qm; }
        }
    }
    __syncthreads();
    if (tid < 128) {
        // combine 4 n-quadrant partials with log2-domain rescale
        float m = sm_mx[0][tid], s = sm_s[0][tid];
        #pragma unroll
        for (int wq = 1; wq < 4; wq++) {
            float mw = sm_mx[wq][tid], sw = sm_s[wq][tid];
            float M = fmaxf(m, mw);
            s = s * ex2f(m - M) + sw * ex2f(mw - M);
            m = M;
        }
        size_t o = (size_t)(m0 + tid) * NTILES + blockIdx.y;
        g_psum[o] = s; g_pmax[o] = m;
    }
}

// ------------------------- K3: per-row loss + prec reduce ------------------
__global__ void reduce_rows_k() {
    int gw = (blockIdx.x * blockDim.x + threadIdx.x) >> 5;  // warp per row
    int lane = threadIdx.x & 31;
    if (gw >= Bn) return;
    float M = NEGBIG, S = 0.f;
    const float* ps = g_psum + (size_t)gw * NTILES;
    const float* pm = g_pmax + (size_t)gw * NTILES;
    for (int t = lane; t < NTILES; t += 32) {
        float mt = pm[t], st = ps[t];
        if (mt > M) { S = S * ex2f(M - mt) + st; M = mt; }
        else        { S += st * ex2f(mt - M); }
    }
    #pragma unroll
    for (int o = 16; o; o >>= 1) {
        float m2 = __shfl_xor_sync(0xffffffffu, M, o);
        float s2 = __shfl_xor_sync(0xffffffffu, S, o);
        float Mn = fmaxf(M, m2);
        S = S * ex2f(M - Mn) + s2 * ex2f(m2 - Mn);
        M = Mn;
    }
    if (lane == 0) {
        g_rowloss[gw] = LN2F * (M + __log2f(S)) - g_tgt[gw];
        g_correct[gw] = (g_tgt[gw] * LOG2E >= M) ? 1 : 0;
    }
}

// ------------------------- K4: copy centers -> out -------------------------
__global__ void copy_centers_k(const float* __restrict__ centers, float* __restrict__ out) {
    size_t i = (size_t)blockIdx.x * blockDim.x + threadIdx.x;   // float2 index
    const float2* src = reinterpret_cast<const float2*>(centers);
    float2* dst = reinterpret_cast<float2*>(out);
    dst[i] = src[i];
}

// ------------------------- K5: scatter update + center loss (fused) --------
__global__ void scatter_closs_k(const float* __restrict__ emb,
                                const float* __restrict__ centers,
                                float* __restrict__ outc) {
    int b = blockIdx.x;
    int r = g_lab[b];
    float coef = ALPHA_C / (g_appear[b] + EPS_C);
    const float* e = emb + (size_t)b * En;
    const float* c = centers + (size_t)r * En;
    float* o = outc + (size_t)r * En;
    float ss = 0.f;
    for (int i = threadIdx.x; i < En; i += 128) {
        float d = e[i] - c[i];
        atomicAdd(&o[i], coef * d);
        ss += d * d;
    }
    #pragma unroll
    for (int of = 16; of; of >>= 1) ss += __shfl_xor_sync(0xffffffffu, ss, of);
    __shared__ float sp[4];
    int warp = threadIdx.x >> 5, lane = threadIdx.x & 31;
    if (lane == 0) sp[warp] = ss;
    __syncthreads();
    if (threadIdx.x == 0)
        atomicAdd(&g_closs, sp[0] + sp[1] + sp[2] + sp[3]);
}

// ------------------------- K6: finalize scalars ----------------------------
__global__ void finalize_k(float* __restrict__ out) {
    int tid = threadIdx.x;  // 512
    float sl = g_rowloss[tid];
    int   sc = g_correct[tid];
    #pragma unroll
    for (int o = 16; o; o >>= 1) {
        sl += __shfl_xor_sync(0xffffffffu, sl, o);
        sc += __shfl_xor_sync(0xffffffffu, sc, o);
    }
    __shared__ float sm_l[16];
    __shared__ int   sm_c[16];
    if ((tid & 31) == 0) { sm_l[tid >> 5] = sl; sm_c[tid >> 5] = sc; }
    __syncthreads();
    if (tid == 0) {
        float L = 0.f; int Cc = 0;
        #pragma unroll
        for (int i = 0; i < 16; i++) { L += sm_l[i]; Cc += sm_c[i]; }
        out[0] = 100.0f * (float)Cc / (float)Bn;
        out[1] = L / (float)Bn + LAMDA * (g_closs / (float)(Bn * En));
    }
}

// ------------------------- launcher ---------------------------------------
extern "C" void kernel_launch(void* const* d_in, const int* in_sizes, int n_in,
                              void* d_out, int out_size) {
    (void)in_sizes; (void)n_in; (void)out_size;
    const float* emb = (const float*)d_in[0];
    const float* w   = (const float*)d_in[1];
    const float* cen = (const float*)d_in[2];
    const void*  lab = d_in[3];
    float* out = (float*)d_out;

    // One-time host objects (created on the first, non-captured correctness
    // call; reused unchanged on the capture call and every replay).
    static bool s_init = false;
    static cudaStream_t s1;
    static cudaEvent_t evFork, evJoin;
    if (!s_init) {
        cudaStreamCreateWithFlags(&s1, cudaStreamNonBlocking);
        cudaEventCreateWithFlags(&evFork, cudaEventDisableTiming);
        cudaEventCreateWithFlags(&evJoin, cudaEventDisableTiming);
        cudaFuncSetAttribute(gemm_softmax_k,
                             cudaFuncAttributeMaxDynamicSharedMemorySize, SMEM_DYN);
        s_init = true;
    }

    // Main branch (default stream): decode -> preps -> gemm -> reduce.
    decode_labels_k<<<1, 256>>>(lab);
    cudaEventRecord(evFork, 0);                       // fork point: labels+closs ready
    prep_emb_k<<<Bn, 128>>>(emb);
    prep_w_k<<<Cn / 8, 256>>>(w);
    gemm_softmax_k<<<dim3(4, NTILES), 256, SMEM_DYN>>>();

    // Side branch (s1): DRAM-bound work hidden under the MUFU-bound gemm.
    cudaStreamWaitEvent(s1, evFork, 0);
    appear_k<<<1, Bn, 0, s1>>>();
    copy_centers_k<<<100000, 256, 0, s1>>>(cen, out + 2);
    scatter_closs_k<<<Bn, 128, 0, s1>>>(emb, cen, out + 2);
    cudaEventRecord(evJoin, s1);

    // Main branch continues.
    tgt_k<<<Bn / 8, 256>>>(emb, w);
    reduce_rows_k<<<64, 256>>>();
    cudaStreamWaitEvent(0, evJoin, 0);                // join before finalize
    finalize_k<<<1, Bn>>>(out);
}

// round 17
// speedup vs baseline: 1.7648x; 1.0463x over previous
#include <cuda_runtime.h>
#include <cuda_bf16.h>
#include <cuda_fp16.h>
#include <math.h>
#include <stdint.h>

// Problem constants
#define Bn 512
#define En 512
#define Cn 100000
#define NTILES 782            // ceil(100000/128)
#define NT_HALF 391
#define S_SCALE 30.0f
#define SM_MARGIN 10.5f       // S*M
#define LAMDA 0.01f
#define ALPHA_C 0.5f
#define EPS_C 1e-6f
#define LOG2E 1.4426950408889634f
#define LN2F 0.6931471805599453f
#define M2_MARGIN (10.5f * 1.4426950408889634f)   // margin in log2 units
#define NEGBIG -1.0e30f

#define SMEM_DYN (2 * 128 * 40 * 2 * 2)           // As+Bs double-buffered = 40960 B

// ------------------------- device scratch (static, no allocation) ----------
__device__ int   g_lab[Bn];
__device__ float g_inv_e[Bn];
__device__ __nv_bfloat16 g_emb_bf[Bn * En];       // emb * (S*log2e*inv_e)  (pre-scaled)
__device__ __nv_bfloat16 g_w_bf[(size_t)Cn * En]; // w * inv_w              (pre-normalized)
__device__ float g_tgt[Bn];
__device__ float g_psum[(size_t)Bn * NTILES];     // raw sumexp2 partials (plain add merge)
__device__ float g_pmax[(size_t)Bn * NTILES];     // raw max partials (log2 units)
__device__ float g_rowloss[Bn];
__device__ int   g_correct[Bn];
__device__ float g_closs;
__device__ float g_appear[Bn];

__device__ __forceinline__ float ex2f(float x) {
    float r;
    asm("ex2.approx.f32 %0, %1;" : "=f"(r) : "f"(x));
    return r;
}

// ------------------------- K-1: decode labels (int32 vs int64 autodetect) --
__global__ void decode_labels_k(const void* __restrict__ labraw) {
    const long long* l64 = (const long long*)labraw;
    const int*       l32 = (const int*)labraw;
    int t = threadIdx.x;               // 256 threads
    long long v = l64[t];              // first 2048 bytes: safe in both layouts
    int valid = (v >= 0 && v < (long long)Cn) ? 1 : 0;
    #pragma unroll
    for (int o = 16; o; o >>= 1) valid &= __shfl_xor_sync(0xffffffffu, valid, o);
    __shared__ int sv[8];
    if ((t & 31) == 0) sv[t >> 5] = valid;
    __syncthreads();
    int all64 = sv[0] & sv[1] & sv[2] & sv[3] & sv[4] & sv[5] & sv[6] & sv[7];
    if (all64) {
        g_lab[t]       = (int)l64[t];
        g_lab[t + 256] = (int)l64[t + 256];
    } else {
        g_lab[t]       = l32[t];
        g_lab[t + 256] = l32[t + 256];
    }
    if (t == 0) g_closs = 0.0f;        // zero BEFORE the stream fork
}

// ------------------------- K0: embedding norms + pre-scaled bf16 -----------
__global__ void prep_emb_k(const float* __restrict__ emb) {
    int b = blockIdx.x;            // 512 blocks
    int t = threadIdx.x;           // 128 threads
    float4 v = reinterpret_cast<const float4*>(emb + (size_t)b * En)[t];
    float ss = v.x * v.x + v.y * v.y + v.z * v.z + v.w * v.w;
    #pragma unroll
    for (int o = 16; o; o >>= 1) ss += __shfl_xor_sync(0xffffffffu, ss, o);
    __shared__ float sp[4];
    if ((t & 31) == 0) sp[t >> 5] = ss;
    __syncthreads();
    float inv = rsqrtf(sp[0] + sp[1] + sp[2] + sp[3]);
    if (t == 0) g_inv_e[b] = inv;
    float sc = S_SCALE * LOG2E * inv;               // fold row scale into A
    __nv_bfloat162* dst = reinterpret_cast<__nv_bfloat162*>(g_emb_bf + (size_t)b * En);
    dst[t * 2]     = __floats2bfloat162_rn(v.x * sc, v.y * sc);
    dst[t * 2 + 1] = __floats2bfloat162_rn(v.z * sc, v.w * sc);
}

// ------------------------- K0b: appear counts ------------------------------
__global__ void appear_k() {
    __shared__ int labs[Bn];
    int t = threadIdx.x;
    labs[t] = g_lab[t];
    __syncthreads();
    int mine = labs[t], cnt = 0;
    #pragma unroll 8
    for (int i = 0; i < Bn; i++) cnt += (labs[i] == mine);
    g_appear[t] = (float)cnt;
}

// ------------------------- K1: weight norm-folded bf16 (warp per row) ------
// Processes rows [row0, row0 + 8*gridDim.x)
__global__ __launch_bounds__(256) void prep_w_k(const float* __restrict__ w, int row0) {
    int warp = threadIdx.x >> 5, lane = threadIdx.x & 31;
    int r = row0 + blockIdx.x * 8 + warp;
    const float4* src = reinterpret_cast<const float4*>(w + (size_t)r * En);
    float4 v[4];
    float ss = 0.f;
    #pragma unroll
    for (int p = 0; p < 4; p++) {
        v[p] = src[lane + p * 32];
        ss += v[p].x * v[p].x + v[p].y * v[p].y + v[p].z * v[p].z + v[p].w * v[p].w;
    }
    #pragma unroll
    for (int o = 16; o; o >>= 1) ss += __shfl_xor_sync(0xffffffffu, ss, o);
    float inv = rsqrtf(ss);                         // all lanes have full sum
    __nv_bfloat162* dst = reinterpret_cast<__nv_bfloat162*>(g_w_bf + (size_t)r * En);
    #pragma unroll
    for (int p = 0; p < 4; p++) {
        dst[(lane + p * 32) * 2]     = __floats2bfloat162_rn(v[p].x * inv, v[p].y * inv);
        dst[(lane + p * 32) * 2 + 1] = __floats2bfloat162_rn(v[p].z * inv, v[p].w * inv);
    }
}

// ------------------------- K1b: exact fp32 target logit (self-norm) --------
__global__ __launch_bounds__(256) void tgt_k(const float* __restrict__ emb,
                                             const float* __restrict__ w) {
    int warp = threadIdx.x >> 5, lane = threadIdx.x & 31;
    int b = blockIdx.x * 8 + warp;          // 64*8 = 512
    int lab = g_lab[b];
    const float4* e4 = reinterpret_cast<const float4*>(emb + (size_t)b * En);
    const float4* w4 = reinterpret_cast<const float4*>(w + (size_t)lab * En);
    float dot = 0.f, ssw = 0.f;
    #pragma unroll
    for (int p = 0; p < 4; p++) {
        float4 a = e4[lane + p * 32];
        float4 c = w4[lane + p * 32];
        dot += a.x * c.x + a.y * c.y + a.z * c.z + a.w * c.w;
        ssw += c.x * c.x + c.y * c.y + c.z * c.z + c.w * c.w;
    }
    #pragma unroll
    for (int o = 16; o; o >>= 1) {
        dot += __shfl_xor_sync(0xffffffffu, dot, o);
        ssw += __shfl_xor_sync(0xffffffffu, ssw, o);
    }
    if (lane == 0)
        g_tgt[b] = S_SCALE * dot * g_inv_e[b] * rsqrtf(ssw) - SM_MARGIN;
}

// ------------------------- K2: bf16 GEMM + raw bf16x2-exp partials ---------
__device__ __forceinline__ void mma16816(float* d, const uint32_t* a, const uint32_t* b) {
    asm volatile(
        "mma.sync.aligned.m16n8k16.row.col.f32.bf16.bf16.f32 "
        "{%0,%1,%2,%3}, {%4,%5,%6,%7}, {%8,%9}, {%0,%1,%2,%3};\n"
        : "+f"(d[0]), "+f"(d[1]), "+f"(d[2]), "+f"(d[3])
        : "r"(a[0]), "r"(a[1]), "r"(a[2]), "r"(a[3]), "r"(b[0]), "r"(b[1]));
}

// grid = (4, NT_HALF), ny = ny_base + blockIdx.y
__global__ __launch_bounds__(256, 2) void gemm_softmax_k(int ny_base) {
    extern __shared__ __align__(16) char dyn[];
    __nv_bfloat16* As = reinterpret_cast<__nv_bfloat16*>(dyn);            // [2][128][40]
    __nv_bfloat16* Bs = reinterpret_cast<__nv_bfloat16*>(dyn + 20480);    // [2][128][40]

    const int tid  = threadIdx.x;
    const int warp = tid >> 5, lane = tid & 31;
    const int wm = warp & 1, wn = warp >> 1;       // warps: 2 (M) x 4 (N)
    const int gid = lane >> 2, t4 = lane & 3;
    const int ny = ny_base + blockIdx.y;
    const int m0 = blockIdx.x * 128, n0 = ny * 128;
    const bool tail = (n0 + 128 > Cn);

    __shared__ float sm_s[4][128], sm_mx[4][128];

    float acc[4][4][4];
    #pragma unroll
    for (int a = 0; a < 4; a++)
        #pragma unroll
        for (int b = 0; b < 4; b++)
            #pragma unroll
            for (int c = 0; c < 4; c++) acc[a][b][c] = 0.f;

    auto load_stage = [&](int st, int kb) {
        #pragma unroll
        for (int i = 0; i < 2; i++) {
            int id  = tid + i * 256;
            int row = id >> 2, seg = id & 3;
            {   // A tile (pre-scaled embedding bf16)
                uint32_t dst = (uint32_t)__cvta_generic_to_shared(&As[(st * 128 + row) * 40 + seg * 8]);
                const void* src = &g_emb_bf[(size_t)(m0 + row) * En + kb + seg * 8];
                asm volatile("cp.async.cg.shared.global [%0], [%1], 16;\n" :: "r"(dst), "l"(src));
            }
            {   // B tile (pre-normalized weights bf16), clamp OOB rows (masked later)
                int gn = n0 + row;
                uint32_t dst = (uint32_t)__cvta_generic_to_shared(&Bs[(st * 128 + row) * 40 + seg * 8]);
                size_t gnc = (gn < Cn) ? (size_t)gn : (size_t)(Cn - 1);
                const void* src = &g_w_bf[gnc * En + kb + seg * 8];
                asm volatile("cp.async.cg.shared.global [%0], [%1], 16;\n" :: "r"(dst), "l"(src));
            }
        }
        asm volatile("cp.async.commit_group;\n");
    };

    load_stage(0, 0);
    load_stage(1, 32);
    #pragma unroll 1
    for (int ks = 0; ks < 16; ks++) {
        int st = ks & 1;
        if (ks < 15) asm volatile("cp.async.wait_group 1;\n");
        else         asm volatile("cp.async.wait_group 0;\n");
        __syncthreads();
        #pragma unroll
        for (int kk = 0; kk < 32; kk += 16) {
            uint32_t afr[4][4], bfr[4][2];
            #pragma unroll
            for (int mt = 0; mt < 4; mt++) {
                int r = wm * 64 + mt * 16 + gid;
                afr[mt][0] = *(const uint32_t*)&As[(st * 128 + r) * 40 + kk + t4 * 2];
                afr[mt][1] = *(const uint32_t*)&As[(st * 128 + r + 8) * 40 + kk + t4 * 2];
                afr[mt][2] = *(const uint32_t*)&As[(st * 128 + r) * 40 + kk + t4 * 2 + 8];
                afr[mt][3] = *(const uint32_t*)&As[(st * 128 + r + 8) * 40 + kk + t4 * 2 + 8];
            }
            #pragma unroll
            for (int nt = 0; nt < 4; nt++) {
                int c = wn * 32 + nt * 8 + gid;
                bfr[nt][0] = *(const uint32_t*)&Bs[(st * 128 + c) * 40 + kk + t4 * 2];
                bfr[nt][1] = *(const uint32_t*)&Bs[(st * 128 + c) * 40 + kk + t4 * 2 + 8];
            }
            #pragma unroll
            for (int mt = 0; mt < 4; mt++)
                #pragma unroll
                for (int nt = 0; nt < 4; nt++)
                    mma16816(acc[mt][nt], afr[mt], bfr[nt]);
        }
        __syncthreads();                       // retire all reads of stage st
        if (ks + 2 < 16) load_stage(st, (ks + 2) * 32);
    }

    // ---- epilogue: acc IS the logit in log2 units. Raw bf16x2 exp2. -------
    #pragma unroll
    for (int mt = 0; mt < 4; mt++) {
        #pragma unroll
        for (int h = 0; h < 2; h++) {
            int row = wm * 64 + mt * 16 + gid + h * 8;
            float v[8];
            #pragma unroll
            for (int nt = 0; nt < 4; nt++) {
                #pragma unroll
                for (int j = 0; j < 2; j++)
                    v[nt * 2 + j] = acc[mt][nt][h * 2 + j];
            }
            if (tail) {
                #pragma unroll
                for (int nt = 0; nt < 4; nt++)
                    #pragma unroll
                    for (int j = 0; j < 2; j++) {
                        int cg = n0 + wn * 32 + nt * 8 + t4 * 2 + j;
                        if (cg >= Cn) v[nt * 2 + j] = NEGBIG;
                    }
            }
            float mx = fmaxf(fmaxf(fmaxf(v[0], v[1]), fmaxf(v[2], v[3])),
                             fmaxf(fmaxf(v[4], v[5]), fmaxf(v[6], v[7])));
            uint32_t acc2 = 0;                 // bf16x2 accumulator (+0,+0)
            #pragma unroll
            for (int p = 0; p < 4; p++) {
                uint32_t bb, ee;
                asm("cvt.rn.bf16x2.f32 %0, %1, %2;" : "=r"(bb) : "f"(v[2 * p + 1]), "f"(v[2 * p]));
                asm("ex2.approx.ftz.bf16x2 %0, %1;" : "=r"(ee) : "r"(bb));
                asm("add.rn.bf16x2 %0, %1, %2;" : "=r"(acc2) : "r"(acc2), "r"(ee));
            }
            __nv_bfloat162 hb = *reinterpret_cast<__nv_bfloat162*>(&acc2);
            float sr = __bfloat162float(hb.x) + __bfloat162float(hb.y);
            sr += __shfl_xor_sync(0xffffffffu, sr, 1);
            sr += __shfl_xor_sync(0xffffffffu, sr, 2);
            mx = fmaxf(mx, __shfl_xor_sync(0xffffffffu, mx, 1));
            mx = fmaxf(mx, __shfl_xor_sync(0xffffffffu, mx, 2));
            if (t4 == 0) { sm_s[wn][row] = sr; sm_mx[wn][row] = mx; }
        }
    }
    __syncthreads();
    if (tid < 128) {
        float s = sm_s[0][tid] + sm_s[1][tid] + sm_s[2][tid] + sm_s[3][tid];
        float m = fmaxf(fmaxf(sm_mx[0][tid], sm_mx[1][tid]),
                        fmaxf(sm_mx[2][tid], sm_mx[3][tid]));
        size_t o = (size_t)(m0 + tid) * NTILES + ny;
        g_psum[o] = s; g_pmax[o] = m;
    }
}

// ------------------------- K3: per-row loss + prec reduce ------------------
__global__ void reduce_rows_k() {
    int gw = (blockIdx.x * blockDim.x + threadIdx.x) >> 5;  // warp per row
    int lane = threadIdx.x & 31;
    if (gw >= Bn) return;
    float S = 0.f, M = NEGBIG;
    const float* ps = g_psum + (size_t)gw * NTILES;
    const float* pm = g_pmax + (size_t)gw * NTILES;
    for (int t = lane; t < NTILES; t += 32) {
        S += ps[t];
        M = fmaxf(M, pm[t]);
    }
    #pragma unroll
    for (int o = 16; o; o >>= 1) {
        S += __shfl_xor_sync(0xffffffffu, S, o);
        M = fmaxf(M, __shfl_xor_sync(0xffffffffu, M, o));
    }
    if (lane == 0) {
        // post-hoc margin correction: swap the unmargined label term for the
        // margined one, both exact fp32 (gemm included the unmargined term).
        float t2m = g_tgt[gw] * LOG2E;                 // margined, log2 units
        float t2n = t2m + M2_MARGIN;                   // unmargined
        S += ex2f(t2m) - ex2f(t2n);
        g_rowloss[gw] = LN2F * __log2f(S) - g_tgt[gw];
        g_correct[gw] = (t2m >= M) ? 1 : 0;
    }
}

// ------------------------- K4: copy centers -> out -------------------------
__global__ void copy_centers_k(const float* __restrict__ centers, float* __restrict__ out) {
    size_t i = (size_t)blockIdx.x * blockDim.x + threadIdx.x;   // float2 index
    const float2* src = reinterpret_cast<const float2*>(centers);
    float2* dst = reinterpret_cast<float2*>(out);
    dst[i] = src[i];
}

// ------------------------- K5: scatter update + center loss (fused) --------
__global__ void scatter_closs_k(const float* __restrict__ emb,
                                const float* __restrict__ centers,
                                float* __restrict__ outc) {
    int b = blockIdx.x;
    int r = g_lab[b];
    float coef = ALPHA_C / (g_appear[b] + EPS_C);
    const float* e = emb + (size_t)b * En;
    const float* c = centers + (size_t)r * En;
    float* o = outc + (size_t)r * En;
    float ss = 0.f;
    for (int i = threadIdx.x; i < En; i += 128) {
        float d = e[i] - c[i];
        atomicAdd(&o[i], coef * d);
        ss += d * d;
    }
    #pragma unroll
    for (int of = 16; of; of >>= 1) ss += __shfl_xor_sync(0xffffffffu, ss, of);
    __shared__ float sp[4];
    int warp = threadIdx.x >> 5, lane = threadIdx.x & 31;
    if (lane == 0) sp[warp] = ss;
    __syncthreads();
    if (threadIdx.x == 0)
        atomicAdd(&g_closs, sp[0] + sp[1] + sp[2] + sp[3]);
}

// ------------------------- K6: finalize scalars ----------------------------
__global__ void finalize_k(float* __restrict__ out) {
    int tid = threadIdx.x;  // 512
    float sl = g_rowloss[tid];
    int   sc = g_correct[tid];
    #pragma unroll
    for (int o = 16; o; o >>= 1) {
        sl += __shfl_xor_sync(0xffffffffu, sl, o);
        sc += __shfl_xor_sync(0xffffffffu, sc, o);
    }
    __shared__ float sm_l[16];
    __shared__ int   sm_c[16];
    if ((tid & 31) == 0) { sm_l[tid >> 5] = sl; sm_c[tid >> 5] = sc; }
    __syncthreads();
    if (tid == 0) {
        float L = 0.f; int Cc = 0;
        #pragma unroll
        for (int i = 0; i < 16; i++) { L += sm_l[i]; Cc += sm_c[i]; }
        out[0] = 100.0f * (float)Cc / (float)Bn;
        out[1] = L / (float)Bn + LAMDA * (g_closs / (float)(Bn * En));
    }
}

// ------------------------- launcher ---------------------------------------
// N split: tiles [0, 391) need W rows [0, 50048); tiles [391, 782) the rest.
#define WA_ROWS 50048
#define WA_BLKS (WA_ROWS / 8)                  // 6256
#define WB_BLKS ((Cn - WA_ROWS) / 8)           // 6244  (49952 rows)

extern "C" void kernel_launch(void* const* d_in, const int* in_sizes, int n_in,
                              void* d_out, int out_size) {
    (void)in_sizes; (void)n_in; (void)out_size;
    const float* emb = (const float*)d_in[0];
    const float* w   = (const float*)d_in[1];
    const float* cen = (const float*)d_in[2];
    const void*  lab = d_in[3];
    float* out = (float*)d_out;

    static bool s_init = false;
    static cudaStream_t s1;
    static cudaEvent_t evFork, evA, evB, evJoin;
    if (!s_init) {
        cudaStreamCreateWithFlags(&s1, cudaStreamNonBlocking);
        cudaEventCreateWithFlags(&evFork, cudaEventDisableTiming);
        cudaEventCreateWithFlags(&evA,    cudaEventDisableTiming);
        cudaEventCreateWithFlags(&evB,    cudaEventDisableTiming);
        cudaEventCreateWithFlags(&evJoin, cudaEventDisableTiming);
        cudaFuncSetAttribute(gemm_softmax_k,
                             cudaFuncAttributeMaxDynamicSharedMemorySize, SMEM_DYN);
        s_init = true;
    }

    // Main stream: decode -> prep_emb -> prep_w(A) -> gemm(A) -> gemm(B)
    decode_labels_k<<<1, 256>>>(lab);
    cudaEventRecord(evFork, 0);
    prep_emb_k<<<Bn, 128>>>(emb);
    prep_w_k<<<WA_BLKS, 256>>>(w, 0);
    cudaEventRecord(evA, 0);                           // W[0:50048) ready
    gemm_softmax_k<<<dim3(4, NT_HALF), 256, SMEM_DYN>>>(0);

    // Side stream: prep_w(B) overlaps gemm(A); then DRAM-bound tail work.
    cudaStreamWaitEvent(s1, evA, 0);                   // after prep_w(A) (BW priority)
    prep_w_k<<<WB_BLKS, 256, 0, s1>>>(w, WA_ROWS);
    cudaEventRecord(evB, s1);                          // W[50048:100000) ready
    appear_k<<<1, Bn, 0, s1>>>();                      // labels ready since evFork<evA
    copy_centers_k<<<100000, 256, 0, s1>>>(cen, out + 2);
    scatter_closs_k<<<Bn, 128, 0, s1>>>(emb, cen, out + 2);
    cudaEventRecord(evJoin, s1);

    // Main stream: second gemm half after its weights are ready.
    cudaStreamWaitEvent(0, evB, 0);
    gemm_softmax_k<<<dim3(4, NT_HALF), 256, SMEM_DYN>>>(NT_HALF);
    tgt_k<<<Bn / 8, 256>>>(emb, w);
    reduce_rows_k<<<64, 256>>>();
    cudaStreamWaitEvent(0, evJoin, 0);
    finalize_k<<<1, Bn>>>(out);
}